// round 2
// baseline (speedup 1.0000x reference)
#include <cuda_runtime.h>
#include <cuda_bf16.h>
#include <math.h>

#define MAXN 50000
#define MAXE 800000
#define F128 128

// ---------------- scratch (device globals; no allocation allowed) ----------
__device__ float g_hs[MAXN * F128];
__device__ float g_acc[MAXN * F128];
__device__ float g_dinv[MAXN];
__device__ int   g_indeg[MAXN];
__device__ int   g_off[MAXN];
__device__ int   g_cur[MAXN];
__device__ int   g_csr[MAXE];
__device__ float g_Wc[F128 * F128];
__device__ float g_bpre[F128];
__device__ int   g_bsum[256];
__device__ int   g_bex[256];

// ---------------- helpers ----------------
__device__ __forceinline__ float4 f4add(float4 a, float4 b) {
    return make_float4(a.x + b.x, a.y + b.y, a.z + b.z, a.w + b.w);
}

__device__ __forceinline__ void atomicMaxFloat(float* addr, float v) {
    if (v >= 0.0f) atomicMax((int*)addr, __float_as_int(v));
    else           atomicMin((unsigned int*)addr, __float_as_uint(v));
}

// packed fp32x2 FMA (sm_100+): d = a * b + d
#define FMA2(d, a, b) \
    asm("fma.rn.f32x2 %0, %1, %2, %0;" : "+l"(d) : "l"(a), "l"(b))
#define PACK2(d, lo, hi) \
    asm("mov.b64 %0, {%1, %2};" : "=l"(d) : "r"(__float_as_uint(lo)), "r"(__float_as_uint(hi)))
#define UNPACK2(lo, hi, d) \
    { unsigned int _l, _h; asm("mov.b64 {%0, %1}, %2;" : "=r"(_l), "=r"(_h) : "l"(d)); \
      lo = __uint_as_float(_l); hi = __uint_as_float(_h); }

// ---------------- preprocessing ----------------
__global__ void k_init_indeg(int N) {
    int n = blockIdx.x * blockDim.x + threadIdx.x;
    if (n < N) g_indeg[n] = 0;
}

__global__ void k_count(const int* __restrict__ ei, int E) {
    int e = blockIdx.x * blockDim.x + threadIdx.x;
    if (e < E) atomicAdd(&g_indeg[ei[E + e]], 1);
}

// block sums via shfl
__global__ void k_scan_p1(int N) {
    int t = threadIdx.x;
    int n = blockIdx.x * 256 + t;
    int v = (n < N) ? g_indeg[n] : 0;
    #pragma unroll
    for (int o = 16; o > 0; o >>= 1) v += __shfl_down_sync(0xffffffffu, v, o);
    __shared__ int ws[8];
    if ((t & 31) == 0) ws[t >> 5] = v;
    __syncthreads();
    if (t < 8) {
        int s = ws[t];
        #pragma unroll
        for (int o = 4; o > 0; o >>= 1) s += __shfl_down_sync(0xffu, s, o);
        if (t == 0) g_bsum[blockIdx.x] = s;
    }
}

// exclusive scan of block sums (single block, NB <= 256)
__global__ void k_scan_p2(int NB) {
    int t = threadIdx.x;
    int lane = t & 31, w = t >> 5;
    int v = (t < NB) ? g_bsum[t] : 0;
    int x = v;
    #pragma unroll
    for (int o = 1; o < 32; o <<= 1) {
        int y = __shfl_up_sync(0xffffffffu, x, o);
        if (lane >= o) x += y;
    }
    __shared__ int ws[8];
    if (lane == 31) ws[w] = x;
    __syncthreads();
    int wo = 0;
    #pragma unroll
    for (int j = 0; j < 8; j++) if (j < w) wo += ws[j];
    g_bex[t] = x - v + wo;   // exclusive prefix
}

// per-block exclusive scan + base; also compute dinv (fold k_dinv)
__global__ void k_scan_p3(int N) {
    int t = threadIdx.x;
    int n = blockIdx.x * 256 + t;
    int lane = t & 31, w = t >> 5;
    int deg = (n < N) ? g_indeg[n] : 0;
    int x = deg;
    #pragma unroll
    for (int o = 1; o < 32; o <<= 1) {
        int y = __shfl_up_sync(0xffffffffu, x, o);
        if (lane >= o) x += y;
    }
    __shared__ int ws[8];
    if (lane == 31) ws[w] = x;
    __syncthreads();
    int wo = 0;
    #pragma unroll
    for (int j = 0; j < 8; j++) if (j < w) wo += ws[j];
    int ex = x - deg + wo + g_bex[blockIdx.x];
    if (n < N) {
        g_off[n] = ex;
        g_cur[n] = ex;
        g_dinv[n] = rsqrtf((float)(deg + 1));
    }
}

__global__ void k_fill(const int* __restrict__ ei, int E) {
    int e = blockIdx.x * blockDim.x + threadIdx.x;
    if (e < E) {
        int src = ei[e];
        int dst = ei[E + e];
        int p = atomicAdd(&g_cur[dst], 1);
        g_csr[p] = src;
    }
}

// ---------------- Wc = Wl @ W2, bpre = bl @ W2 ----------------
__global__ void k_wc(const float* __restrict__ Wl, const float* __restrict__ bl,
                     const float* __restrict__ W2) {
    int idx = blockIdx.x * blockDim.x + threadIdx.x;
    if (idx < F128 * F128) {
        int r = idx >> 7, c = idx & 127;
        float s = 0.0f;
        #pragma unroll 8
        for (int k = 0; k < F128; k++) s += Wl[r * F128 + k] * W2[k * F128 + c];
        g_Wc[idx] = s;
    }
    if (idx < F128) {
        float s = 0.0f;
        #pragma unroll 8
        for (int k = 0; k < F128; k++) s += bl[k] * W2[k * F128 + idx];
        g_bpre[idx] = s;
    }
}

// ---------------- GEMM 1: hs = (x @ W1) * dinv[row] ----------------
// 256 threads, 64 rows x 128 cols, KT=32. As stored TRANSPOSED: As[k][r].
// FFMA2 over row-pairs: ld.shared.b64 gives {a_r, a_r+1}.
__global__ void k_gemm1(const float* __restrict__ A, const float* __restrict__ B, int N) {
    __shared__ float As[32 * 64];     // [k][r]
    __shared__ float Bs[32 * 128];    // [k][c]
    int tid = threadIdx.x;
    int tc = tid & 31, tr = tid >> 5;
    int row0 = blockIdx.x * 64;
    unsigned long long acc2[4][4] = {};   // [row-pair][col] = {r0,r1}

    int lr = tid & 63;              // load row within tile
    int kc = (tid >> 6) * 8;        // load k-chunk
    int gr = row0 + lr;

    for (int k0 = 0; k0 < 128; k0 += 32) {
        {
            float4 v0 = make_float4(0, 0, 0, 0), v1 = make_float4(0, 0, 0, 0);
            if (gr < N) {
                v0 = *(const float4*)(A + gr * 128 + k0 + kc);
                v1 = *(const float4*)(A + gr * 128 + k0 + kc + 4);
            }
            As[(kc + 0) * 64 + lr] = v0.x; As[(kc + 1) * 64 + lr] = v0.y;
            As[(kc + 2) * 64 + lr] = v0.z; As[(kc + 3) * 64 + lr] = v0.w;
            As[(kc + 4) * 64 + lr] = v1.x; As[(kc + 5) * 64 + lr] = v1.y;
            As[(kc + 6) * 64 + lr] = v1.z; As[(kc + 7) * 64 + lr] = v1.w;
        }
        {
            const float4* Bg = (const float4*)(B + k0 * 128);
            float4* Bs4 = (float4*)Bs;
            #pragma unroll
            for (int it = 0; it < 4; it++) Bs4[tid + 256 * it] = Bg[tid + 256 * it];
        }
        __syncthreads();
        #pragma unroll
        for (int k = 0; k < 32; k++) {
            float4 b4 = *(const float4*)(Bs + k * 128 + tc * 4);
            unsigned long long bb[4];
            PACK2(bb[0], b4.x, b4.x); PACK2(bb[1], b4.y, b4.y);
            PACK2(bb[2], b4.z, b4.z); PACK2(bb[3], b4.w, b4.w);
            #pragma unroll
            for (int i2 = 0; i2 < 4; i2++) {
                unsigned long long ap = *(const unsigned long long*)(As + k * 64 + tr * 8 + 2 * i2);
                FMA2(acc2[i2][0], ap, bb[0]);
                FMA2(acc2[i2][1], ap, bb[1]);
                FMA2(acc2[i2][2], ap, bb[2]);
                FMA2(acc2[i2][3], ap, bb[3]);
            }
        }
        __syncthreads();
    }
    #pragma unroll
    for (int i2 = 0; i2 < 4; i2++) {
        float lo[4], hi[4];
        #pragma unroll
        for (int c = 0; c < 4; c++) UNPACK2(lo[c], hi[c], acc2[i2][c]);
        int r0 = row0 + tr * 8 + 2 * i2;
        if (r0 < N) {
            float dv = g_dinv[r0];
            *(float4*)(g_hs + r0 * 128 + tc * 4) =
                make_float4(lo[0] * dv, lo[1] * dv, lo[2] * dv, lo[3] * dv);
        }
        if (r0 + 1 < N) {
            float dv = g_dinv[r0 + 1];
            *(float4*)(g_hs + (r0 + 1) * 128 + tc * 4) =
                make_float4(hi[0] * dv, hi[1] * dv, hi[2] * dv, hi[3] * dv);
        }
    }
}

// ---------------- GEMM 2: hs = (tanh(dinv*acc + b1) @ Wc + bpre) * dinv ----
__global__ void k_gemm2(const float* __restrict__ b1, int N) {
    __shared__ float As[32 * 64];
    __shared__ float Bs[32 * 128];
    int tid = threadIdx.x;
    int tc = tid & 31, tr = tid >> 5;
    int row0 = blockIdx.x * 64;
    unsigned long long acc2[4][4] = {};

    int lr = tid & 63;
    int kc = (tid >> 6) * 8;
    int gr = row0 + lr;
    float dvr = (gr < N) ? g_dinv[gr] : 0.0f;

    for (int k0 = 0; k0 < 128; k0 += 32) {
        {
            float4 v0 = make_float4(0, 0, 0, 0), v1 = make_float4(0, 0, 0, 0);
            if (gr < N) {
                float4 a0 = *(const float4*)(g_acc + gr * 128 + k0 + kc);
                float4 a1 = *(const float4*)(g_acc + gr * 128 + k0 + kc + 4);
                float4 q0 = *(const float4*)(b1 + k0 + kc);
                float4 q1 = *(const float4*)(b1 + k0 + kc + 4);
                v0 = make_float4(tanhf(dvr * a0.x + q0.x), tanhf(dvr * a0.y + q0.y),
                                 tanhf(dvr * a0.z + q0.z), tanhf(dvr * a0.w + q0.w));
                v1 = make_float4(tanhf(dvr * a1.x + q1.x), tanhf(dvr * a1.y + q1.y),
                                 tanhf(dvr * a1.z + q1.z), tanhf(dvr * a1.w + q1.w));
            }
            As[(kc + 0) * 64 + lr] = v0.x; As[(kc + 1) * 64 + lr] = v0.y;
            As[(kc + 2) * 64 + lr] = v0.z; As[(kc + 3) * 64 + lr] = v0.w;
            As[(kc + 4) * 64 + lr] = v1.x; As[(kc + 5) * 64 + lr] = v1.y;
            As[(kc + 6) * 64 + lr] = v1.z; As[(kc + 7) * 64 + lr] = v1.w;
        }
        {
            const float4* Bg = (const float4*)(g_Wc + k0 * 128);
            float4* Bs4 = (float4*)Bs;
            #pragma unroll
            for (int it = 0; it < 4; it++) Bs4[tid + 256 * it] = Bg[tid + 256 * it];
        }
        __syncthreads();
        #pragma unroll
        for (int k = 0; k < 32; k++) {
            float4 b4 = *(const float4*)(Bs + k * 128 + tc * 4);
            unsigned long long bb[4];
            PACK2(bb[0], b4.x, b4.x); PACK2(bb[1], b4.y, b4.y);
            PACK2(bb[2], b4.z, b4.z); PACK2(bb[3], b4.w, b4.w);
            #pragma unroll
            for (int i2 = 0; i2 < 4; i2++) {
                unsigned long long ap = *(const unsigned long long*)(As + k * 64 + tr * 8 + 2 * i2);
                FMA2(acc2[i2][0], ap, bb[0]);
                FMA2(acc2[i2][1], ap, bb[1]);
                FMA2(acc2[i2][2], ap, bb[2]);
                FMA2(acc2[i2][3], ap, bb[3]);
            }
        }
        __syncthreads();
    }
    float4 bp = *(const float4*)(g_bpre + tc * 4);
    #pragma unroll
    for (int i2 = 0; i2 < 4; i2++) {
        float lo[4], hi[4];
        #pragma unroll
        for (int c = 0; c < 4; c++) UNPACK2(lo[c], hi[c], acc2[i2][c]);
        int r0 = row0 + tr * 8 + 2 * i2;
        if (r0 < N) {
            float dv = g_dinv[r0];
            *(float4*)(g_hs + r0 * 128 + tc * 4) =
                make_float4((lo[0] + bp.x) * dv, (lo[1] + bp.y) * dv,
                            (lo[2] + bp.z) * dv, (lo[3] + bp.w) * dv);
        }
        if (r0 + 1 < N) {
            float dv = g_dinv[r0 + 1];
            *(float4*)(g_hs + (r0 + 1) * 128 + tc * 4) =
                make_float4((hi[0] + bp.x) * dv, (hi[1] + bp.y) * dv,
                            (hi[2] + bp.z) * dv, (hi[3] + bp.w) * dv);
        }
    }
}

// ---------------- Aggregation: acc[n] = hs[n] + sum_{in-edges} hs[src] -----
__global__ void k_agg(int N) {
    int gw = (blockIdx.x * blockDim.x + threadIdx.x) >> 5;
    int lane = threadIdx.x & 31;
    if (gw >= N) return;
    const float4* hs4 = (const float4*)g_hs;
    float4* acc4 = (float4*)g_acc;
    int beg = g_off[gw];
    int cnt = g_indeg[gw];
    float4 s = hs4[gw * 32 + lane];
    int j = 0;
    for (; j + 4 <= cnt; j += 4) {
        int s0 = g_csr[beg + j];
        int s1 = g_csr[beg + j + 1];
        int s2 = g_csr[beg + j + 2];
        int s3 = g_csr[beg + j + 3];
        float4 a = hs4[s0 * 32 + lane];
        float4 b = hs4[s1 * 32 + lane];
        float4 c = hs4[s2 * 32 + lane];
        float4 d = hs4[s3 * 32 + lane];
        s = f4add(s, f4add(f4add(a, b), f4add(c, d)));
    }
    for (; j < cnt; j++) s = f4add(s, hs4[g_csr[beg + j] * 32 + lane]);
    acc4[gw * 32 + lane] = s;
}

// ---------------- Final: out = max_n( tanh(dinv*acc + b2) @ Wo + bo ) ------
// 64 rows x 64 cols, KT=32, 256 threads; 2 cols/thread, FFMA2 row-pairs.
__global__ void k_final(const float* __restrict__ b2, const float* __restrict__ Wo,
                        const float* __restrict__ bo, float* __restrict__ out, int N) {
    __shared__ float As[32 * 64];
    __shared__ float Bs[32 * 64];
    int tid = threadIdx.x;
    int tc = tid & 31, tr = tid >> 5;
    int row0 = blockIdx.x * 64;
    unsigned long long acc2[4][2] = {};

    int lr = tid & 63;
    int kc = (tid >> 6) * 8;
    int gr = row0 + lr;
    float dvr = (gr < N) ? g_dinv[gr] : 0.0f;

    for (int k0 = 0; k0 < 128; k0 += 32) {
        {
            float4 v0 = make_float4(0, 0, 0, 0), v1 = make_float4(0, 0, 0, 0);
            if (gr < N) {
                float4 a0 = *(const float4*)(g_acc + gr * 128 + k0 + kc);
                float4 a1 = *(const float4*)(g_acc + gr * 128 + k0 + kc + 4);
                float4 q0 = *(const float4*)(b2 + k0 + kc);
                float4 q1 = *(const float4*)(b2 + k0 + kc + 4);
                v0 = make_float4(tanhf(dvr * a0.x + q0.x), tanhf(dvr * a0.y + q0.y),
                                 tanhf(dvr * a0.z + q0.z), tanhf(dvr * a0.w + q0.w));
                v1 = make_float4(tanhf(dvr * a1.x + q1.x), tanhf(dvr * a1.y + q1.y),
                                 tanhf(dvr * a1.z + q1.z), tanhf(dvr * a1.w + q1.w));
            }
            As[(kc + 0) * 64 + lr] = v0.x; As[(kc + 1) * 64 + lr] = v0.y;
            As[(kc + 2) * 64 + lr] = v0.z; As[(kc + 3) * 64 + lr] = v0.w;
            As[(kc + 4) * 64 + lr] = v1.x; As[(kc + 5) * 64 + lr] = v1.y;
            As[(kc + 6) * 64 + lr] = v1.z; As[(kc + 7) * 64 + lr] = v1.w;
        }
        {
            const float4* Bg = (const float4*)(Wo + k0 * 64);
            float4* Bs4 = (float4*)Bs;
            Bs4[tid] = Bg[tid];
            Bs4[tid + 256] = Bg[tid + 256];
        }
        __syncthreads();
        #pragma unroll
        for (int k = 0; k < 32; k++) {
            float2 b2v = *(const float2*)(Bs + k * 64 + tc * 2);
            unsigned long long bb[2];
            PACK2(bb[0], b2v.x, b2v.x); PACK2(bb[1], b2v.y, b2v.y);
            #pragma unroll
            for (int i2 = 0; i2 < 4; i2++) {
                unsigned long long ap = *(const unsigned long long*)(As + k * 64 + tr * 8 + 2 * i2);
                FMA2(acc2[i2][0], ap, bb[0]);
                FMA2(acc2[i2][1], ap, bb[1]);
            }
        }
        __syncthreads();
    }
    float bo0 = bo[tc * 2], bo1 = bo[tc * 2 + 1];
    float m0 = -INFINITY, m1 = -INFINITY;
    #pragma unroll
    for (int i2 = 0; i2 < 4; i2++) {
        float lo0, hi0, lo1, hi1;
        UNPACK2(lo0, hi0, acc2[i2][0]);
        UNPACK2(lo1, hi1, acc2[i2][1]);
        int r0 = row0 + tr * 8 + 2 * i2;
        if (r0 < N)     { m0 = fmaxf(m0, lo0 + bo0); m1 = fmaxf(m1, lo1 + bo1); }
        if (r0 + 1 < N) { m0 = fmaxf(m0, hi0 + bo0); m1 = fmaxf(m1, hi1 + bo1); }
    }
    As[tr * 64 + tc * 2] = m0;
    As[tr * 64 + tc * 2 + 1] = m1;
    __syncthreads();
    if (tid < 64) {
        float m = As[tid];
        #pragma unroll
        for (int j = 1; j < 8; j++) m = fmaxf(m, As[j * 64 + tid]);
        atomicMaxFloat(&out[tid], m);
    }
}

__global__ void k_init_out(float* out) {
    int t = threadIdx.x;
    if (t < 64) out[t] = -INFINITY;
}

// ---------------- launch ----------------
extern "C" void kernel_launch(void* const* d_in, const int* in_sizes, int n_in,
                              void* d_out, int out_size) {
    const float* x  = (const float*)d_in[0];
    const int*   ei = (const int*)d_in[1];
    const float* W1 = (const float*)d_in[2];
    const float* b1 = (const float*)d_in[3];
    const float* Wl = (const float*)d_in[4];
    const float* bl = (const float*)d_in[5];
    const float* W2 = (const float*)d_in[6];
    const float* b2 = (const float*)d_in[7];
    const float* Wo = (const float*)d_in[8];
    const float* bo = (const float*)d_in[9];
    float* out = (float*)d_out;

    int N = in_sizes[0] / F128;   // 50000
    int E = in_sizes[1] / 2;      // 800000

    int nbN = (N + 255) / 256;    // 196
    int nbE = (E + 255) / 256;

    k_init_indeg<<<nbN, 256>>>(N);
    k_count<<<nbE, 256>>>(ei, E);
    k_scan_p1<<<nbN, 256>>>(N);
    k_scan_p2<<<1, 256>>>(nbN);
    k_scan_p3<<<nbN, 256>>>(N);
    k_fill<<<nbE, 256>>>(ei, E);
    k_wc<<<(F128 * F128 + 255) / 256, 256>>>(Wl, bl, W2);

    int nbG = (N + 63) / 64;      // 782
    int nbA = (N + 7) / 8;        // 6250

    k_gemm1<<<nbG, 256>>>(x, W1, N);
    k_agg<<<nbA, 256>>>(N);
    k_gemm2<<<nbG, 256>>>(b1, N);
    k_agg<<<nbA, 256>>>(N);
    k_init_out<<<1, 64>>>(out);
    k_final<<<nbG, 256>>>(b2, Wo, bo, out, N);
}

// round 3
// speedup vs baseline: 1.1670x; 1.1670x over previous
#include <cuda_runtime.h>
#include <cuda_bf16.h>
#include <math.h>

#define MAXN 50000
#define MAXE 800000
#define F128 128

// ---------------- scratch (device globals; no allocation allowed) ----------
__device__ float g_hs[MAXN * F128];
__device__ float g_acc[MAXN * F128];
__device__ float g_dinv[MAXN];
__device__ int   g_indeg[MAXN];
__device__ int   g_off[MAXN];
__device__ int   g_cur[MAXN];
__device__ int   g_csr[MAXE];
__device__ float g_Wc[F128 * F128];
__device__ float g_bpre[F128];
__device__ int   g_bsum[256];
__device__ int   g_bex[256];

// ---------------- helpers ----------------
__device__ __forceinline__ float4 f4add(float4 a, float4 b) {
    return make_float4(a.x + b.x, a.y + b.y, a.z + b.z, a.w + b.w);
}

__device__ __forceinline__ void atomicMaxFloat(float* addr, float v) {
    if (v >= 0.0f) atomicMax((int*)addr, __float_as_int(v));
    else           atomicMin((unsigned int*)addr, __float_as_uint(v));
}

// round-to-nearest tf32 (keeps bits in a float slot)
__device__ __forceinline__ float tf32r(float x) {
    unsigned u;
    asm("cvt.rna.tf32.f32 %0, %1;" : "=r"(u) : "f"(x));
    return __uint_as_float(u);
}

// m16n8k8 tf32 mma: D += A*B  (row.col)
__device__ __forceinline__ void mma_tf32(float* c, const unsigned* a, const unsigned* b) {
    asm("mma.sync.aligned.m16n8k8.row.col.f32.tf32.tf32.f32 "
        "{%0,%1,%2,%3}, {%4,%5,%6,%7}, {%8,%9}, {%0,%1,%2,%3};"
        : "+f"(c[0]), "+f"(c[1]), "+f"(c[2]), "+f"(c[3])
        : "r"(a[0]), "r"(a[1]), "r"(a[2]), "r"(a[3]), "r"(b[0]), "r"(b[1]));
}

// packed fp32x2 FMA (kept for k_final)
#define FMA2(d, a, b) \
    asm("fma.rn.f32x2 %0, %1, %2, %0;" : "+l"(d) : "l"(a), "l"(b))
#define PACK2(d, lo, hi) \
    asm("mov.b64 %0, {%1, %2};" : "=l"(d) : "r"(__float_as_uint(lo)), "r"(__float_as_uint(hi)))
#define UNPACK2(lo, hi, d) \
    { unsigned int _l, _h; asm("mov.b64 {%0, %1}, %2;" : "=r"(_l), "=r"(_h) : "l"(d)); \
      lo = __uint_as_float(_l); hi = __uint_as_float(_h); }

// ---------------- preprocessing ----------------
__global__ void k_init_indeg(int N) {
    int n = blockIdx.x * blockDim.x + threadIdx.x;
    if (n < N) g_indeg[n] = 0;
}

__global__ void k_count(const int* __restrict__ ei, int E) {
    int e = blockIdx.x * blockDim.x + threadIdx.x;
    if (e < E) atomicAdd(&g_indeg[ei[E + e]], 1);
}

__global__ void k_dinv(int N) {
    int n = blockIdx.x * blockDim.x + threadIdx.x;
    if (n < N) g_dinv[n] = rsqrtf((float)(g_indeg[n] + 1));
}

__global__ void k_scan_p1(int N) {
    int t = threadIdx.x;
    int n = blockIdx.x * 256 + t;
    int v = (n < N) ? g_indeg[n] : 0;
    #pragma unroll
    for (int o = 16; o > 0; o >>= 1) v += __shfl_down_sync(0xffffffffu, v, o);
    __shared__ int ws[8];
    if ((t & 31) == 0) ws[t >> 5] = v;
    __syncthreads();
    if (t < 8) {
        int s = ws[t];
        #pragma unroll
        for (int o = 4; o > 0; o >>= 1) s += __shfl_down_sync(0xffu, s, o);
        if (t == 0) g_bsum[blockIdx.x] = s;
    }
}

__global__ void k_scan_p2(int NB) {
    int t = threadIdx.x;
    int lane = t & 31, w = t >> 5;
    int v = (t < NB) ? g_bsum[t] : 0;
    int x = v;
    #pragma unroll
    for (int o = 1; o < 32; o <<= 1) {
        int y = __shfl_up_sync(0xffffffffu, x, o);
        if (lane >= o) x += y;
    }
    __shared__ int ws[8];
    if (lane == 31) ws[w] = x;
    __syncthreads();
    int wo = 0;
    #pragma unroll
    for (int j = 0; j < 8; j++) if (j < w) wo += ws[j];
    g_bex[t] = x - v + wo;
}

__global__ void k_scan_p3(int N) {
    int t = threadIdx.x;
    int n = blockIdx.x * 256 + t;
    int lane = t & 31, w = t >> 5;
    int deg = (n < N) ? g_indeg[n] : 0;
    int x = deg;
    #pragma unroll
    for (int o = 1; o < 32; o <<= 1) {
        int y = __shfl_up_sync(0xffffffffu, x, o);
        if (lane >= o) x += y;
    }
    __shared__ int ws[8];
    if (lane == 31) ws[w] = x;
    __syncthreads();
    int wo = 0;
    #pragma unroll
    for (int j = 0; j < 8; j++) if (j < w) wo += ws[j];
    int ex = x - deg + wo + g_bex[blockIdx.x];
    if (n < N) { g_off[n] = ex; g_cur[n] = ex; }
}

__global__ void k_fill(const int* __restrict__ ei, int E) {
    int e = blockIdx.x * blockDim.x + threadIdx.x;
    if (e < E) {
        int src = ei[e];
        int dst = ei[E + e];
        int p = atomicAdd(&g_cur[dst], 1);
        g_csr[p] = src;
    }
}

// ---------------- Wc = Wl @ W2 (fp32), bpre = bl @ W2 ----------------
__global__ void k_wc(const float* __restrict__ Wl, const float* __restrict__ bl,
                     const float* __restrict__ W2) {
    int idx = blockIdx.x * blockDim.x + threadIdx.x;
    if (idx < F128 * F128) {
        int r = idx >> 7, c = idx & 127;
        float s = 0.0f;
        #pragma unroll 8
        for (int k = 0; k < F128; k++) s += Wl[r * F128 + k] * W2[k * F128 + c];
        g_Wc[idx] = s;
    }
    if (idx < F128) {
        float s = 0.0f;
        #pragma unroll 8
        for (int k = 0; k < F128; k++) s += bl[k] * W2[k * F128 + idx];
        g_bpre[idx] = s;
    }
}

// ================== tf32 MMA GEMM: 64x128 tile, 8 warps ====================
// As: [k][m] 32x64 tf32, XOR-swizzle m ^= (k&3)<<3
// Bs: [k][n] 32x128 tf32, XOR-swizzle n ^= (k&3)<<3
// Warp w: wm=w&1 (rows wm*32..+31), wn=w>>1 (cols wn*32..+31)
// Per warp: 2 m-tiles x 4 n-tiles of m16n8k8.

// ---------------- GEMM 1: hs = (x @ W1) * dinv[row] ----------------
__global__ void k_gemm1(const float* __restrict__ A, const float* __restrict__ B, int N) {
    __shared__ float As[32 * 64];
    __shared__ float Bs[32 * 128];
    int tid = threadIdx.x;
    int lane = tid & 31, w = tid >> 5;
    int wm = w & 1, wn = w >> 1;
    int q = lane >> 2, t = lane & 3;
    int row0 = blockIdx.x * 64;
    float c[2][4][4] = {};

    int lr = tid & 63;
    int kc = (tid >> 6) * 8;
    int gr = row0 + lr;

    for (int k0 = 0; k0 < 128; k0 += 32) {
        // stage A transposed + swizzled + tf32
        {
            float4 v0 = make_float4(0, 0, 0, 0), v1 = make_float4(0, 0, 0, 0);
            if (gr < N) {
                v0 = *(const float4*)(A + gr * 128 + k0 + kc);
                v1 = *(const float4*)(A + gr * 128 + k0 + kc + 4);
            }
            float vv[8] = {v0.x, v0.y, v0.z, v0.w, v1.x, v1.y, v1.z, v1.w};
            #pragma unroll
            for (int j = 0; j < 8; j++) {
                int k = kc + j;
                As[k * 64 + (lr ^ ((k & 3) << 3))] = tf32r(vv[j]);
            }
        }
        // stage B swizzled + tf32
        {
            const float4* Bg = (const float4*)(B + k0 * 128);
            #pragma unroll
            for (int it = 0; it < 4; it++) {
                int idx = tid + 256 * it;
                int k = idx >> 5, c4 = idx & 31;
                float4 bv = Bg[idx];
                bv.x = tf32r(bv.x); bv.y = tf32r(bv.y);
                bv.z = tf32r(bv.z); bv.w = tf32r(bv.w);
                *(float4*)(Bs + k * 128 + ((c4 * 4) ^ ((k & 3) << 3))) = bv;
            }
        }
        __syncthreads();
        #pragma unroll
        for (int ks = 0; ks < 4; ks++) {
            int k = ks * 8 + t;
            int sw = t << 3;
            unsigned a[2][4], b[4][2];
            #pragma unroll
            for (int mt = 0; mt < 2; mt++) {
                int m0 = wm * 32 + mt * 16;
                a[mt][0] = __float_as_uint(As[k * 64 + ((m0 + q) ^ sw)]);
                a[mt][1] = __float_as_uint(As[k * 64 + ((m0 + q + 8) ^ sw)]);
                a[mt][2] = __float_as_uint(As[(k + 4) * 64 + ((m0 + q) ^ sw)]);
                a[mt][3] = __float_as_uint(As[(k + 4) * 64 + ((m0 + q + 8) ^ sw)]);
            }
            #pragma unroll
            for (int nt = 0; nt < 4; nt++) {
                int n0 = wn * 32 + nt * 8 + q;
                b[nt][0] = __float_as_uint(Bs[k * 128 + (n0 ^ sw)]);
                b[nt][1] = __float_as_uint(Bs[(k + 4) * 128 + (n0 ^ sw)]);
            }
            #pragma unroll
            for (int mt = 0; mt < 2; mt++)
                #pragma unroll
                for (int nt = 0; nt < 4; nt++)
                    mma_tf32(c[mt][nt], a[mt], b[nt]);
        }
        __syncthreads();
    }
    // epilogue: *dinv, store
    #pragma unroll
    for (int mt = 0; mt < 2; mt++) {
        #pragma unroll
        for (int half = 0; half < 2; half++) {
            int r = row0 + wm * 32 + mt * 16 + q + half * 8;
            if (r < N) {
                float dv = g_dinv[r];
                #pragma unroll
                for (int nt = 0; nt < 4; nt++) {
                    int col = wn * 32 + nt * 8 + 2 * t;
                    float2 o = make_float2(c[mt][nt][half * 2] * dv,
                                           c[mt][nt][half * 2 + 1] * dv);
                    *(float2*)(g_hs + r * 128 + col) = o;
                }
            }
        }
    }
}

// ---------------- GEMM 2: hs = (tanh(dinv*acc + b1) @ Wc + bpre) * dinv ----
__global__ void k_gemm2(const float* __restrict__ b1, int N) {
    __shared__ float As[32 * 64];
    __shared__ float Bs[32 * 128];
    int tid = threadIdx.x;
    int lane = tid & 31, w = tid >> 5;
    int wm = w & 1, wn = w >> 1;
    int q = lane >> 2, t = lane & 3;
    int row0 = blockIdx.x * 64;
    float c[2][4][4] = {};

    int lr = tid & 63;
    int kc = (tid >> 6) * 8;
    int gr = row0 + lr;
    float dvr = (gr < N) ? g_dinv[gr] : 0.0f;

    for (int k0 = 0; k0 < 128; k0 += 32) {
        {
            float vv[8] = {};
            if (gr < N) {
                float4 a0 = *(const float4*)(g_acc + gr * 128 + k0 + kc);
                float4 a1 = *(const float4*)(g_acc + gr * 128 + k0 + kc + 4);
                float4 q0 = *(const float4*)(b1 + k0 + kc);
                float4 q1 = *(const float4*)(b1 + k0 + kc + 4);
                vv[0] = tanhf(dvr * a0.x + q0.x); vv[1] = tanhf(dvr * a0.y + q0.y);
                vv[2] = tanhf(dvr * a0.z + q0.z); vv[3] = tanhf(dvr * a0.w + q0.w);
                vv[4] = tanhf(dvr * a1.x + q1.x); vv[5] = tanhf(dvr * a1.y + q1.y);
                vv[6] = tanhf(dvr * a1.z + q1.z); vv[7] = tanhf(dvr * a1.w + q1.w);
            }
            #pragma unroll
            for (int j = 0; j < 8; j++) {
                int k = kc + j;
                As[k * 64 + (lr ^ ((k & 3) << 3))] = tf32r(vv[j]);
            }
        }
        {
            const float4* Bg = (const float4*)(g_Wc + k0 * 128);
            #pragma unroll
            for (int it = 0; it < 4; it++) {
                int idx = tid + 256 * it;
                int k = idx >> 5, c4 = idx & 31;
                float4 bv = Bg[idx];
                bv.x = tf32r(bv.x); bv.y = tf32r(bv.y);
                bv.z = tf32r(bv.z); bv.w = tf32r(bv.w);
                *(float4*)(Bs + k * 128 + ((c4 * 4) ^ ((k & 3) << 3))) = bv;
            }
        }
        __syncthreads();
        #pragma unroll
        for (int ks = 0; ks < 4; ks++) {
            int k = ks * 8 + t;
            int sw = t << 3;
            unsigned a[2][4], b[4][2];
            #pragma unroll
            for (int mt = 0; mt < 2; mt++) {
                int m0 = wm * 32 + mt * 16;
                a[mt][0] = __float_as_uint(As[k * 64 + ((m0 + q) ^ sw)]);
                a[mt][1] = __float_as_uint(As[k * 64 + ((m0 + q + 8) ^ sw)]);
                a[mt][2] = __float_as_uint(As[(k + 4) * 64 + ((m0 + q) ^ sw)]);
                a[mt][3] = __float_as_uint(As[(k + 4) * 64 + ((m0 + q + 8) ^ sw)]);
            }
            #pragma unroll
            for (int nt = 0; nt < 4; nt++) {
                int n0 = wn * 32 + nt * 8 + q;
                b[nt][0] = __float_as_uint(Bs[k * 128 + (n0 ^ sw)]);
                b[nt][1] = __float_as_uint(Bs[(k + 4) * 128 + (n0 ^ sw)]);
            }
            #pragma unroll
            for (int mt = 0; mt < 2; mt++)
                #pragma unroll
                for (int nt = 0; nt < 4; nt++)
                    mma_tf32(c[mt][nt], a[mt], b[nt]);
        }
        __syncthreads();
    }
    #pragma unroll
    for (int mt = 0; mt < 2; mt++) {
        #pragma unroll
        for (int half = 0; half < 2; half++) {
            int r = row0 + wm * 32 + mt * 16 + q + half * 8;
            if (r < N) {
                float dv = g_dinv[r];
                #pragma unroll
                for (int nt = 0; nt < 4; nt++) {
                    int col = wn * 32 + nt * 8 + 2 * t;
                    float2 bp = *(const float2*)(g_bpre + col);
                    float2 o = make_float2((c[mt][nt][half * 2] + bp.x) * dv,
                                           (c[mt][nt][half * 2 + 1] + bp.y) * dv);
                    *(float2*)(g_hs + r * 128 + col) = o;
                }
            }
        }
    }
}

// ---------------- Aggregation: acc[n] = hs[n] + sum_{in-edges} hs[src] -----
__global__ void k_agg(int N) {
    int gw = (blockIdx.x * blockDim.x + threadIdx.x) >> 5;
    int lane = threadIdx.x & 31;
    if (gw >= N) return;
    const float4* hs4 = (const float4*)g_hs;
    float4* acc4 = (float4*)g_acc;
    int beg = g_off[gw];
    int cnt = g_indeg[gw];
    float4 s = hs4[gw * 32 + lane];
    int j = 0;
    for (; j + 4 <= cnt; j += 4) {
        int s0 = g_csr[beg + j];
        int s1 = g_csr[beg + j + 1];
        int s2 = g_csr[beg + j + 2];
        int s3 = g_csr[beg + j + 3];
        float4 a = hs4[s0 * 32 + lane];
        float4 b = hs4[s1 * 32 + lane];
        float4 c = hs4[s2 * 32 + lane];
        float4 d = hs4[s3 * 32 + lane];
        s = f4add(s, f4add(f4add(a, b), f4add(c, d)));
    }
    for (; j < cnt; j++) s = f4add(s, hs4[g_csr[beg + j] * 32 + lane]);
    acc4[gw * 32 + lane] = s;
}

// ---------------- Final: out = max_n( tanh(dinv*acc + b2) @ Wo + bo ) ------
// full fp32 (FFMA2) to keep the unattenuated last-layer error at 1e-7
__global__ void k_final(const float* __restrict__ b2, const float* __restrict__ Wo,
                        const float* __restrict__ bo, float* __restrict__ out, int N) {
    __shared__ float As[32 * 64];
    __shared__ float Bs[32 * 64];
    int tid = threadIdx.x;
    int tc = tid & 31, tr = tid >> 5;
    int row0 = blockIdx.x * 64;
    unsigned long long acc2[4][2] = {};

    int lr = tid & 63;
    int kc = (tid >> 6) * 8;
    int gr = row0 + lr;
    float dvr = (gr < N) ? g_dinv[gr] : 0.0f;

    for (int k0 = 0; k0 < 128; k0 += 32) {
        {
            float4 v0 = make_float4(0, 0, 0, 0), v1 = make_float4(0, 0, 0, 0);
            if (gr < N) {
                float4 a0 = *(const float4*)(g_acc + gr * 128 + k0 + kc);
                float4 a1 = *(const float4*)(g_acc + gr * 128 + k0 + kc + 4);
                float4 q0 = *(const float4*)(b2 + k0 + kc);
                float4 q1 = *(const float4*)(b2 + k0 + kc + 4);
                v0 = make_float4(tanhf(dvr * a0.x + q0.x), tanhf(dvr * a0.y + q0.y),
                                 tanhf(dvr * a0.z + q0.z), tanhf(dvr * a0.w + q0.w));
                v1 = make_float4(tanhf(dvr * a1.x + q1.x), tanhf(dvr * a1.y + q1.y),
                                 tanhf(dvr * a1.z + q1.z), tanhf(dvr * a1.w + q1.w));
            }
            As[(kc + 0) * 64 + lr] = v0.x; As[(kc + 1) * 64 + lr] = v0.y;
            As[(kc + 2) * 64 + lr] = v0.z; As[(kc + 3) * 64 + lr] = v0.w;
            As[(kc + 4) * 64 + lr] = v1.x; As[(kc + 5) * 64 + lr] = v1.y;
            As[(kc + 6) * 64 + lr] = v1.z; As[(kc + 7) * 64 + lr] = v1.w;
        }
        {
            const float4* Bg = (const float4*)(Wo + k0 * 64);
            float4* Bs4 = (float4*)Bs;
            Bs4[tid] = Bg[tid];
            Bs4[tid + 256] = Bg[tid + 256];
        }
        __syncthreads();
        #pragma unroll
        for (int k = 0; k < 32; k++) {
            float2 b2v = *(const float2*)(Bs + k * 64 + tc * 2);
            unsigned long long bb[2];
            PACK2(bb[0], b2v.x, b2v.x); PACK2(bb[1], b2v.y, b2v.y);
            #pragma unroll
            for (int i2 = 0; i2 < 4; i2++) {
                unsigned long long ap = *(const unsigned long long*)(As + k * 64 + tr * 8 + 2 * i2);
                FMA2(acc2[i2][0], ap, bb[0]);
                FMA2(acc2[i2][1], ap, bb[1]);
            }
        }
        __syncthreads();
    }
    float bo0 = bo[tc * 2], bo1 = bo[tc * 2 + 1];
    float m0 = -INFINITY, m1 = -INFINITY;
    #pragma unroll
    for (int i2 = 0; i2 < 4; i2++) {
        float lo0, hi0, lo1, hi1;
        UNPACK2(lo0, hi0, acc2[i2][0]);
        UNPACK2(lo1, hi1, acc2[i2][1]);
        int r0 = row0 + tr * 8 + 2 * i2;
        if (r0 < N)     { m0 = fmaxf(m0, lo0 + bo0); m1 = fmaxf(m1, lo1 + bo1); }
        if (r0 + 1 < N) { m0 = fmaxf(m0, hi0 + bo0); m1 = fmaxf(m1, hi1 + bo1); }
    }
    As[tr * 64 + tc * 2] = m0;
    As[tr * 64 + tc * 2 + 1] = m1;
    __syncthreads();
    if (tid < 64) {
        float m = As[tid];
        #pragma unroll
        for (int j = 1; j < 8; j++) m = fmaxf(m, As[j * 64 + tid]);
        atomicMaxFloat(&out[tid], m);
    }
}

__global__ void k_init_out(float* out) {
    int t = threadIdx.x;
    if (t < 64) out[t] = -INFINITY;
}

// ---------------- launch ----------------
extern "C" void kernel_launch(void* const* d_in, const int* in_sizes, int n_in,
                              void* d_out, int out_size) {
    const float* x  = (const float*)d_in[0];
    const int*   ei = (const int*)d_in[1];
    const float* W1 = (const float*)d_in[2];
    const float* b1 = (const float*)d_in[3];
    const float* Wl = (const float*)d_in[4];
    const float* bl = (const float*)d_in[5];
    const float* W2 = (const float*)d_in[6];
    const float* b2 = (const float*)d_in[7];
    const float* Wo = (const float*)d_in[8];
    const float* bo = (const float*)d_in[9];
    float* out = (float*)d_out;

    int N = in_sizes[0] / F128;   // 50000
    int E = in_sizes[1] / 2;      // 800000

    int nbN = (N + 255) / 256;
    int nbE = (E + 255) / 256;
    int nbG = (N + 63) / 64;
    int nbA = (N + 7) / 8;

    // NOTE: order chosen so the ncu capture (launch #4) is k_gemm1.
    k_init_indeg<<<nbN, 256>>>(N);        // 1
    k_count<<<nbE, 256>>>(ei, E);         // 2
    k_dinv<<<nbN, 256>>>(N);              // 3
    k_gemm1<<<nbG, 256>>>(x, W1, N);      // 4  <- profiled
    k_scan_p1<<<nbN, 256>>>(N);           // 5
    k_scan_p2<<<1, 256>>>(nbN);           // 6
    k_scan_p3<<<nbN, 256>>>(N);           // 7
    k_fill<<<nbE, 256>>>(ei, E);          // 8
    k_wc<<<(F128 * F128 + 255) / 256, 256>>>(Wl, bl, W2);  // 9
    k_agg<<<nbA, 256>>>(N);               // 10
    k_gemm2<<<nbG, 256>>>(b1, N);         // 11
    k_agg<<<nbA, 256>>>(N);               // 12
    k_init_out<<<1, 64>>>(out);           // 13
    k_final<<<nbG, 256>>>(b2, Wo, bo, out, N);  // 14
}

// round 4
// speedup vs baseline: 1.2642x; 1.0833x over previous
#include <cuda_runtime.h>
#include <cuda_bf16.h>
#include <math.h>

#define MAXN 50000
#define MAXE 800000
#define F128 128

// ---------------- scratch (device globals; no allocation allowed) ----------
__device__ __nv_bfloat16 g_hsb[MAXN * F128];  // hs in bf16 (layer outputs pre-agg)
__device__ float g_acc[MAXN * F128];          // fp32 aggregation result
__device__ float g_dinv[MAXN];
__device__ int   g_indeg[MAXN];
__device__ int   g_off[MAXN];
__device__ int   g_cur[MAXN];
__device__ int   g_csr[MAXE];
__device__ float g_Wc[F128 * F128];
__device__ float g_bpre[F128];
__device__ int   g_bsum[256];
__device__ int   g_bex[256];

// ---------------- helpers ----------------
__device__ __forceinline__ float4 f4add(float4 a, float4 b) {
    return make_float4(a.x + b.x, a.y + b.y, a.z + b.z, a.w + b.w);
}

__device__ __forceinline__ void atomicMaxFloat(float* addr, float v) {
    if (v >= 0.0f) atomicMax((int*)addr, __float_as_int(v));
    else           atomicMin((unsigned int*)addr, __float_as_uint(v));
}

// pack 2 floats -> bf16x2 (lo = first source's LOW half)
__device__ __forceinline__ unsigned cvt_bf2(float hi, float lo) {
    unsigned d;
    asm("cvt.rn.bf16x2.f32 %0, %1, %2;" : "=r"(d) : "f"(hi), "f"(lo));
    return d;
}

__device__ __forceinline__ float4 b2f4(uint2 u) {
    __nv_bfloat162 p0 = *reinterpret_cast<__nv_bfloat162*>(&u.x);
    __nv_bfloat162 p1 = *reinterpret_cast<__nv_bfloat162*>(&u.y);
    float2 f0 = __bfloat1622float2(p0);
    float2 f1 = __bfloat1622float2(p1);
    return make_float4(f0.x, f0.y, f1.x, f1.y);
}

__device__ __forceinline__ unsigned sm_u32(const void* p) {
    return (unsigned)__cvta_generic_to_shared(p);
}

#define LDSM_X4(r0, r1, r2, r3, addr) \
    asm volatile("ldmatrix.sync.aligned.m8n8.x4.shared.b16 {%0,%1,%2,%3}, [%4];" \
        : "=r"(r0), "=r"(r1), "=r"(r2), "=r"(r3) : "r"(addr))
#define LDSM_X4T(r0, r1, r2, r3, addr) \
    asm volatile("ldmatrix.sync.aligned.m8n8.x4.trans.shared.b16 {%0,%1,%2,%3}, [%4];" \
        : "=r"(r0), "=r"(r1), "=r"(r2), "=r"(r3) : "r"(addr))

// m16n8k16 bf16 mma, fp32 accumulate
__device__ __forceinline__ void mma_bf16(float* c, const unsigned* a, const unsigned* b) {
    asm("mma.sync.aligned.m16n8k16.row.col.f32.bf16.bf16.f32 "
        "{%0,%1,%2,%3}, {%4,%5,%6,%7}, {%8,%9}, {%0,%1,%2,%3};"
        : "+f"(c[0]), "+f"(c[1]), "+f"(c[2]), "+f"(c[3])
        : "r"(a[0]), "r"(a[1]), "r"(a[2]), "r"(a[3]), "r"(b[0]), "r"(b[1]));
}

// packed fp32x2 FMA (k_final)
#define FMA2(d, a, b) \
    asm("fma.rn.f32x2 %0, %1, %2, %0;" : "+l"(d) : "l"(a), "l"(b))
#define PACK2(d, lo, hi) \
    asm("mov.b64 %0, {%1, %2};" : "=l"(d) : "r"(__float_as_uint(lo)), "r"(__float_as_uint(hi)))
#define UNPACK2(lo, hi, d) \
    { unsigned int _l, _h; asm("mov.b64 {%0, %1}, %2;" : "=r"(_l), "=r"(_h) : "l"(d)); \
      lo = __uint_as_float(_l); hi = __uint_as_float(_h); }

// ---------------- preprocessing ----------------
__global__ void k_init_indeg(int N) {
    int n = blockIdx.x * blockDim.x + threadIdx.x;
    if (n < N) g_indeg[n] = 0;
}

__global__ void k_count(const int* __restrict__ ei, int E) {
    int e = blockIdx.x * blockDim.x + threadIdx.x;
    if (e < E) atomicAdd(&g_indeg[ei[E + e]], 1);
}

__global__ void k_dinv(int N) {
    int n = blockIdx.x * blockDim.x + threadIdx.x;
    if (n < N) g_dinv[n] = rsqrtf((float)(g_indeg[n] + 1));
}

__global__ void k_scan_p1(int N) {
    int t = threadIdx.x;
    int n = blockIdx.x * 256 + t;
    int v = (n < N) ? g_indeg[n] : 0;
    #pragma unroll
    for (int o = 16; o > 0; o >>= 1) v += __shfl_down_sync(0xffffffffu, v, o);
    __shared__ int ws[8];
    if ((t & 31) == 0) ws[t >> 5] = v;
    __syncthreads();
    if (t < 8) {
        int s = ws[t];
        #pragma unroll
        for (int o = 4; o > 0; o >>= 1) s += __shfl_down_sync(0xffu, s, o);
        if (t == 0) g_bsum[blockIdx.x] = s;
    }
}

__global__ void k_scan_p2(int NB) {
    int t = threadIdx.x;
    int lane = t & 31, w = t >> 5;
    int v = (t < NB) ? g_bsum[t] : 0;
    int x = v;
    #pragma unroll
    for (int o = 1; o < 32; o <<= 1) {
        int y = __shfl_up_sync(0xffffffffu, x, o);
        if (lane >= o) x += y;
    }
    __shared__ int ws[8];
    if (lane == 31) ws[w] = x;
    __syncthreads();
    int wo = 0;
    #pragma unroll
    for (int j = 0; j < 8; j++) if (j < w) wo += ws[j];
    g_bex[t] = x - v + wo;
}

__global__ void k_scan_p3(int N) {
    int t = threadIdx.x;
    int n = blockIdx.x * 256 + t;
    int lane = t & 31, w = t >> 5;
    int deg = (n < N) ? g_indeg[n] : 0;
    int x = deg;
    #pragma unroll
    for (int o = 1; o < 32; o <<= 1) {
        int y = __shfl_up_sync(0xffffffffu, x, o);
        if (lane >= o) x += y;
    }
    __shared__ int ws[8];
    if (lane == 31) ws[w] = x;
    __syncthreads();
    int wo = 0;
    #pragma unroll
    for (int j = 0; j < 8; j++) if (j < w) wo += ws[j];
    int ex = x - deg + wo + g_bex[blockIdx.x];
    if (n < N) { g_off[n] = ex; g_cur[n] = ex; }
}

__global__ void k_fill(const int* __restrict__ ei, int E) {
    int e = blockIdx.x * blockDim.x + threadIdx.x;
    if (e < E) {
        int src = ei[e];
        int dst = ei[E + e];
        int p = atomicAdd(&g_cur[dst], 1);
        g_csr[p] = src;
    }
}

// ---------------- Wc = Wl @ W2 (fp32), bpre = bl @ W2 ----------------
__global__ void k_wc(const float* __restrict__ Wl, const float* __restrict__ bl,
                     const float* __restrict__ W2) {
    int idx = blockIdx.x * blockDim.x + threadIdx.x;
    if (idx < F128 * F128) {
        int r = idx >> 7, c = idx & 127;
        float s = 0.0f;
        #pragma unroll 8
        for (int k = 0; k < F128; k++) s += Wl[r * F128 + k] * W2[k * F128 + c];
        g_Wc[idx] = s;
    }
    if (idx < F128) {
        float s = 0.0f;
        #pragma unroll 8
        for (int k = 0; k < F128; k++) s += bl[k] * W2[k * F128 + idx];
        g_bpre[idx] = s;
    }
}

// ============== bf16 MMA GEMM: 64(M)x128(N)xK128, 8 warps =================
// sA: bf16 [m=64][k=128], row pitch 256B, 16B-chunk swizzle: chunk' = c ^ (m&7)
// sB: bf16 [k=128][n=128], row pitch 256B, chunk' = c ^ (k&7)
// Warp w: wm=w&1 -> rows wm*32..+31 ; wn=w>>1 -> cols wn*32..+31
// Fragments via ldmatrix.x4 (A) / ldmatrix.x4.trans (B); 8 k16 steps.

struct MmaCtx {
    unsigned aBase0, aBase1;  // per-mt lane base (row part)
    int m70, m71, thA;
    unsigned bBase0, bBase1;  // per-LDSM lane base (includes swizzle)
};

__device__ __forceinline__ MmaCtx mma_setup(const char* sA, const char* sB,
                                            int lane, int wm, int wn) {
    MmaCtx cx;
    int tl = lane >> 3, li = lane & 7;
    int mA0 = wm * 32 + li + (tl & 1) * 8;
    int mA1 = mA0 + 16;
    cx.m70 = mA0 & 7;
    cx.m71 = mA1 & 7;
    cx.thA = tl >> 1;
    cx.aBase0 = sm_u32(sA) + mA0 * 256;
    cx.aBase1 = sm_u32(sA) + mA1 * 256;
    int klB = li + (tl & 1) * 8;
    int nch0 = wn * 4 + (tl >> 1);
    int nch1 = nch0 + 2;
    cx.bBase0 = sm_u32(sB) + klB * 256 + ((nch0 ^ (klB & 7)) << 4);
    cx.bBase1 = sm_u32(sB) + klB * 256 + ((nch1 ^ (klB & 7)) << 4);
    return cx;
}

__device__ __forceinline__ void mma_mainloop(const MmaCtx& cx, float c[2][4][4]) {
    #pragma unroll
    for (int s = 0; s < 8; s++) {
        unsigned a0[4], a1[4], b[4][2];
        LDSM_X4(a0[0], a0[1], a0[2], a0[3],
                cx.aBase0 + (((2 * s + cx.thA) ^ cx.m70) << 4));
        LDSM_X4(a1[0], a1[1], a1[2], a1[3],
                cx.aBase1 + (((2 * s + cx.thA) ^ cx.m71) << 4));
        LDSM_X4T(b[0][0], b[0][1], b[1][0], b[1][1], cx.bBase0 + s * 4096);
        LDSM_X4T(b[2][0], b[2][1], b[3][0], b[3][1], cx.bBase1 + s * 4096);
        #pragma unroll
        for (int nt = 0; nt < 4; nt++) {
            mma_bf16(c[0][nt], a0, b[nt]);
            mma_bf16(c[1][nt], a1, b[nt]);
        }
    }
}

// stage B: fp32 [128][128] gmem -> bf16 swizzled sB
__device__ __forceinline__ void stage_B(char* sB, const float* __restrict__ Bsrc, int tid) {
    int kk = tid & 127;
    int cb = (tid >> 7) * 8;
    #pragma unroll
    for (int i = 0; i < 8; i++) {
        int c = cb + i;
        float4 v0 = *(const float4*)(Bsrc + kk * 128 + c * 8);
        float4 v1 = *(const float4*)(Bsrc + kk * 128 + c * 8 + 4);
        uint4 u;
        u.x = cvt_bf2(v0.y, v0.x); u.y = cvt_bf2(v0.w, v0.z);
        u.z = cvt_bf2(v1.y, v1.x); u.w = cvt_bf2(v1.w, v1.z);
        *(uint4*)(sB + kk * 256 + ((c ^ (kk & 7)) << 4)) = u;
    }
}

// ---------------- GEMM 1: hsb = bf16( (x @ W1) * dinv[row] ) ---------------
__global__ __launch_bounds__(256) void k_gemm1(const float* __restrict__ A,
                                               const float* __restrict__ B, int N) {
    __shared__ __align__(16) char sA[64 * 256];
    __shared__ __align__(16) char sB[128 * 256];
    int tid = threadIdx.x;
    int lane = tid & 31, w = tid >> 5;
    int wm = w & 1, wn = w >> 1;
    int q = lane >> 2, t = lane & 3;
    int row0 = blockIdx.x * 64;
    float c[2][4][4] = {};

    // stage A (64 x 128 fp32 -> bf16)
    {
        int lr = tid & 63;
        int cb = (tid >> 6) * 4;
        int gr = row0 + lr;
        #pragma unroll
        for (int i = 0; i < 4; i++) {
            int ch = cb + i;
            float4 v0 = make_float4(0, 0, 0, 0), v1 = make_float4(0, 0, 0, 0);
            if (gr < N) {
                v0 = *(const float4*)(A + gr * 128 + ch * 8);
                v1 = *(const float4*)(A + gr * 128 + ch * 8 + 4);
            }
            uint4 u;
            u.x = cvt_bf2(v0.y, v0.x); u.y = cvt_bf2(v0.w, v0.z);
            u.z = cvt_bf2(v1.y, v1.x); u.w = cvt_bf2(v1.w, v1.z);
            *(uint4*)(sA + lr * 256 + ((ch ^ (lr & 7)) << 4)) = u;
        }
    }
    stage_B(sB, B, tid);
    __syncthreads();

    MmaCtx cx = mma_setup(sA, sB, lane, wm, wn);
    mma_mainloop(cx, c);

    // epilogue: *dinv, cvt bf16, store
    #pragma unroll
    for (int mt = 0; mt < 2; mt++) {
        #pragma unroll
        for (int half = 0; half < 2; half++) {
            int r = row0 + wm * 32 + mt * 16 + q + half * 8;
            if (r < N) {
                float dv = g_dinv[r];
                #pragma unroll
                for (int nt = 0; nt < 4; nt++) {
                    int col = wn * 32 + nt * 8 + 2 * t;
                    float lo = c[mt][nt][half * 2] * dv;
                    float hi = c[mt][nt][half * 2 + 1] * dv;
                    *(unsigned*)(&g_hsb[r * 128 + col]) = cvt_bf2(hi, lo);
                }
            }
        }
    }
}

// ------- GEMM 2: hsb = bf16( (tanh(dinv*acc + b1) @ Wc + bpre) * dinv ) ----
__global__ __launch_bounds__(256) void k_gemm2(const float* __restrict__ b1, int N) {
    __shared__ __align__(16) char sA[64 * 256];
    __shared__ __align__(16) char sB[128 * 256];
    int tid = threadIdx.x;
    int lane = tid & 31, w = tid >> 5;
    int wm = w & 1, wn = w >> 1;
    int q = lane >> 2, t = lane & 3;
    int row0 = blockIdx.x * 64;
    float c[2][4][4] = {};

    {
        int lr = tid & 63;
        int cb = (tid >> 6) * 4;
        int gr = row0 + lr;
        float dv = (gr < N) ? g_dinv[gr] : 0.0f;
        #pragma unroll
        for (int i = 0; i < 4; i++) {
            int ch = cb + i;
            float vv[8] = {};
            if (gr < N) {
                float4 a0 = *(const float4*)(g_acc + gr * 128 + ch * 8);
                float4 a1 = *(const float4*)(g_acc + gr * 128 + ch * 8 + 4);
                float4 q0 = *(const float4*)(b1 + ch * 8);
                float4 q1 = *(const float4*)(b1 + ch * 8 + 4);
                vv[0] = tanhf(dv * a0.x + q0.x); vv[1] = tanhf(dv * a0.y + q0.y);
                vv[2] = tanhf(dv * a0.z + q0.z); vv[3] = tanhf(dv * a0.w + q0.w);
                vv[4] = tanhf(dv * a1.x + q1.x); vv[5] = tanhf(dv * a1.y + q1.y);
                vv[6] = tanhf(dv * a1.z + q1.z); vv[7] = tanhf(dv * a1.w + q1.w);
            }
            uint4 u;
            u.x = cvt_bf2(vv[1], vv[0]); u.y = cvt_bf2(vv[3], vv[2]);
            u.z = cvt_bf2(vv[5], vv[4]); u.w = cvt_bf2(vv[7], vv[6]);
            *(uint4*)(sA + lr * 256 + ((ch ^ (lr & 7)) << 4)) = u;
        }
    }
    stage_B(sB, g_Wc, tid);
    __syncthreads();

    MmaCtx cx = mma_setup(sA, sB, lane, wm, wn);
    mma_mainloop(cx, c);

    #pragma unroll
    for (int mt = 0; mt < 2; mt++) {
        #pragma unroll
        for (int half = 0; half < 2; half++) {
            int r = row0 + wm * 32 + mt * 16 + q + half * 8;
            if (r < N) {
                float dv = g_dinv[r];
                #pragma unroll
                for (int nt = 0; nt < 4; nt++) {
                    int col = wn * 32 + nt * 8 + 2 * t;
                    float2 bp = *(const float2*)(g_bpre + col);
                    float lo = (c[mt][nt][half * 2] + bp.x) * dv;
                    float hi = (c[mt][nt][half * 2 + 1] + bp.y) * dv;
                    *(unsigned*)(&g_hsb[r * 128 + col]) = cvt_bf2(hi, lo);
                }
            }
        }
    }
}

// -------- Aggregation: acc[n] = hsb[n] + sum_{in-edges} hsb[src] (fp32) ----
__global__ void k_agg(int N) {
    int gw = (blockIdx.x * blockDim.x + threadIdx.x) >> 5;
    int lane = threadIdx.x & 31;
    if (gw >= N) return;
    const uint2* hsb = (const uint2*)g_hsb;   // 8B per lane = 4 bf16
    int beg = g_off[gw];
    int cnt = g_indeg[gw];
    float4 s = b2f4(hsb[gw * 32 + lane]);     // self loop term
    int j = 0;
    for (; j + 4 <= cnt; j += 4) {
        int s0 = g_csr[beg + j];
        int s1 = g_csr[beg + j + 1];
        int s2 = g_csr[beg + j + 2];
        int s3 = g_csr[beg + j + 3];
        float4 a = b2f4(hsb[s0 * 32 + lane]);
        float4 b = b2f4(hsb[s1 * 32 + lane]);
        float4 c = b2f4(hsb[s2 * 32 + lane]);
        float4 d = b2f4(hsb[s3 * 32 + lane]);
        s = f4add(s, f4add(f4add(a, b), f4add(c, d)));
    }
    for (; j < cnt; j++) s = f4add(s, b2f4(hsb[g_csr[beg + j] * 32 + lane]));
    ((float4*)g_acc)[gw * 32 + lane] = s;
}

// ---------------- Final: out = max_n( tanh(dinv*acc + b2) @ Wo + bo ) ------
// full fp32 (FFMA2) — unattenuated last layer
__global__ void k_final(const float* __restrict__ b2, const float* __restrict__ Wo,
                        const float* __restrict__ bo, float* __restrict__ out, int N) {
    __shared__ float As[32 * 64];
    __shared__ float Bs[32 * 64];
    int tid = threadIdx.x;
    int tc = tid & 31, tr = tid >> 5;
    int row0 = blockIdx.x * 64;
    unsigned long long acc2[4][2] = {};

    int lr = tid & 63;
    int kc = (tid >> 6) * 8;
    int gr = row0 + lr;
    float dvr = (gr < N) ? g_dinv[gr] : 0.0f;

    for (int k0 = 0; k0 < 128; k0 += 32) {
        {
            float4 v0 = make_float4(0, 0, 0, 0), v1 = make_float4(0, 0, 0, 0);
            if (gr < N) {
                float4 a0 = *(const float4*)(g_acc + gr * 128 + k0 + kc);
                float4 a1 = *(const float4*)(g_acc + gr * 128 + k0 + kc + 4);
                float4 q0 = *(const float4*)(b2 + k0 + kc);
                float4 q1 = *(const float4*)(b2 + k0 + kc + 4);
                v0 = make_float4(tanhf(dvr * a0.x + q0.x), tanhf(dvr * a0.y + q0.y),
                                 tanhf(dvr * a0.z + q0.z), tanhf(dvr * a0.w + q0.w));
                v1 = make_float4(tanhf(dvr * a1.x + q1.x), tanhf(dvr * a1.y + q1.y),
                                 tanhf(dvr * a1.z + q1.z), tanhf(dvr * a1.w + q1.w));
            }
            As[(kc + 0) * 64 + lr] = v0.x; As[(kc + 1) * 64 + lr] = v0.y;
            As[(kc + 2) * 64 + lr] = v0.z; As[(kc + 3) * 64 + lr] = v0.w;
            As[(kc + 4) * 64 + lr] = v1.x; As[(kc + 5) * 64 + lr] = v1.y;
            As[(kc + 6) * 64 + lr] = v1.z; As[(kc + 7) * 64 + lr] = v1.w;
        }
        {
            const float4* Bg = (const float4*)(Wo + k0 * 64);
            float4* Bs4 = (float4*)Bs;
            Bs4[tid] = Bg[tid];
            Bs4[tid + 256] = Bg[tid + 256];
        }
        __syncthreads();
        #pragma unroll
        for (int k = 0; k < 32; k++) {
            float2 b2v = *(const float2*)(Bs + k * 64 + tc * 2);
            unsigned long long bb[2];
            PACK2(bb[0], b2v.x, b2v.x); PACK2(bb[1], b2v.y, b2v.y);
            #pragma unroll
            for (int i2 = 0; i2 < 4; i2++) {
                unsigned long long ap = *(const unsigned long long*)(As + k * 64 + tr * 8 + 2 * i2);
                FMA2(acc2[i2][0], ap, bb[0]);
                FMA2(acc2[i2][1], ap, bb[1]);
            }
        }
        __syncthreads();
    }
    float bo0 = bo[tc * 2], bo1 = bo[tc * 2 + 1];
    float m0 = -INFINITY, m1 = -INFINITY;
    #pragma unroll
    for (int i2 = 0; i2 < 4; i2++) {
        float lo0, hi0, lo1, hi1;
        UNPACK2(lo0, hi0, acc2[i2][0]);
        UNPACK2(lo1, hi1, acc2[i2][1]);
        int r0 = row0 + tr * 8 + 2 * i2;
        if (r0 < N)     { m0 = fmaxf(m0, lo0 + bo0); m1 = fmaxf(m1, lo1 + bo1); }
        if (r0 + 1 < N) { m0 = fmaxf(m0, hi0 + bo0); m1 = fmaxf(m1, hi1 + bo1); }
    }
    As[tr * 64 + tc * 2] = m0;
    As[tr * 64 + tc * 2 + 1] = m1;
    __syncthreads();
    if (tid < 64) {
        float m = As[tid];
        #pragma unroll
        for (int j = 1; j < 8; j++) m = fmaxf(m, As[j * 64 + tid]);
        atomicMaxFloat(&out[tid], m);
    }
}

__global__ void k_init_out(float* out) {
    int t = threadIdx.x;
    if (t < 64) out[t] = -INFINITY;
}

// ---------------- launch ----------------
extern "C" void kernel_launch(void* const* d_in, const int* in_sizes, int n_in,
                              void* d_out, int out_size) {
    const float* x  = (const float*)d_in[0];
    const int*   ei = (const int*)d_in[1];
    const float* W1 = (const float*)d_in[2];
    const float* b1 = (const float*)d_in[3];
    const float* Wl = (const float*)d_in[4];
    const float* bl = (const float*)d_in[5];
    const float* W2 = (const float*)d_in[6];
    const float* b2 = (const float*)d_in[7];
    const float* Wo = (const float*)d_in[8];
    const float* bo = (const float*)d_in[9];
    float* out = (float*)d_out;

    int N = in_sizes[0] / F128;   // 50000
    int E = in_sizes[1] / 2;      // 800000

    int nbN = (N + 255) / 256;
    int nbE = (E + 255) / 256;
    int nbG = (N + 63) / 64;
    int nbA = (N + 7) / 8;

    // launch #4 is k_gemm1 (profiled by ncu -s 5 -c 1)
    k_init_indeg<<<nbN, 256>>>(N);        // 1
    k_count<<<nbE, 256>>>(ei, E);         // 2
    k_dinv<<<nbN, 256>>>(N);              // 3
    k_gemm1<<<nbG, 256>>>(x, W1, N);      // 4  <- profiled
    k_scan_p1<<<nbN, 256>>>(N);           // 5
    k_scan_p2<<<1, 256>>>(nbN);           // 6
    k_scan_p3<<<nbN, 256>>>(N);           // 7
    k_fill<<<nbE, 256>>>(ei, E);          // 8
    k_wc<<<(F128 * F128 + 255) / 256, 256>>>(Wl, bl, W2);  // 9
    k_agg<<<nbA, 256>>>(N);               // 10
    k_gemm2<<<nbG, 256>>>(b1, N);         // 11
    k_agg<<<nbA, 256>>>(N);               // 12
    k_init_out<<<1, 64>>>(out);           // 13
    k_final<<<nbG, 256>>>(b2, Wo, bo, out, N);  // 14
}